// round 1
// baseline (speedup 1.0000x reference)
#include <cuda_runtime.h>
#include <math.h>

#define N_NODES 50000
#define N_EDGES 800000
#define IN_F    128
#define HID     32
#define HEADS   8
#define HF      256          // HEADS*HID
#define N_CLASSES 40
#define NEG_SLOPE 0.2f

// ---------------- scratch (device globals; no allocation allowed) ----------------
__device__ float g_P[N_NODES * HF];          // projected features
__device__ float g_Q[N_NODES * HF];          // aggregated features
__device__ float g_el[N_NODES * HEADS];
__device__ float g_er[N_NODES * HEADS];
__device__ float g_o1[N_NODES * N_CLASSES];  // output-layer projection
__device__ float g_o2[N_NODES * N_CLASSES];  // output-layer aggregation
__device__ int   g_cnt[N_NODES];
__device__ int   g_cur[N_NODES];
__device__ int   g_off[N_NODES + 1];
__device__ int   g_ssrc[N_EDGES];

// ---------------- CSR build: histogram -> scan -> scatter ----------------
__global__ void hist_k(const int* __restrict__ dst) {
    int i = blockIdx.x * blockDim.x + threadIdx.x;
    if (i < N_EDGES) atomicAdd(&g_cnt[dst[i]], 1);
}

__global__ void scan_k() {   // one block, 1024 threads
    __shared__ int sh[1024];
    int t = threadIdx.x;
    const int n = N_NODES;
    const int chunk = (n + 1023) / 1024;
    int lo = t * chunk;
    int hi = lo + chunk; if (hi > n) hi = n;
    int s = 0;
    for (int i = lo; i < hi; i++) s += g_cnt[i];
    sh[t] = s;
    __syncthreads();
    int own = s;
    for (int d = 1; d < 1024; d <<= 1) {
        int v = (t >= d) ? sh[t - d] : 0;
        __syncthreads();
        sh[t] += v;
        __syncthreads();
    }
    int base = sh[t] - own;
    for (int i = lo; i < hi; i++) { g_off[i] = base; base += g_cnt[i]; }
    if (t == 1023) g_off[n] = sh[1023];
}

__global__ void scatter_k(const int* __restrict__ src, const int* __restrict__ dst) {
    int i = blockIdx.x * blockDim.x + threadIdx.x;
    if (i < N_EDGES) {
        int d = dst[i];
        int pos = atomicAdd(&g_cur[d], 1);
        g_ssrc[g_off[d] + pos] = src[i];
    }
}

// ---------------- fp32 tiled GEMM: C[M,N] = A[M,K] @ B[K,N] ----------------
#define BM 64
#define BN 64
#define BK 16
__global__ void gemm_k(const float* __restrict__ A, const float* __restrict__ B,
                       float* __restrict__ C, int M, int N, int K) {
    __shared__ float As[BK][BM + 1];
    __shared__ float Bs[BK][BN];
    int tid = threadIdx.x;
    int tx = tid % 16, ty = tid / 16;
    int row0 = blockIdx.y * BM;
    int col0 = blockIdx.x * BN;
    float acc[4][4] = {};
    for (int k0 = 0; k0 < K; k0 += BK) {
        for (int t = tid; t < BM * BK; t += 256) {
            int m = t / BK, kk = t % BK;
            int gr = row0 + m;
            As[kk][m] = (gr < M) ? A[(size_t)gr * K + k0 + kk] : 0.f;
        }
        for (int t = tid; t < BK * BN; t += 256) {
            int kk = t / BN, c = t % BN;
            int gc = col0 + c;
            Bs[kk][c] = (gc < N) ? B[(size_t)(k0 + kk) * N + gc] : 0.f;
        }
        __syncthreads();
        #pragma unroll
        for (int kk = 0; kk < BK; kk++) {
            float a[4], b[4];
            #pragma unroll
            for (int i = 0; i < 4; i++) a[i] = As[kk][ty * 4 + i];
            #pragma unroll
            for (int j = 0; j < 4; j++) b[j] = Bs[kk][tx * 4 + j];
            #pragma unroll
            for (int i = 0; i < 4; i++)
                #pragma unroll
                for (int j = 0; j < 4; j++)
                    acc[i][j] += a[i] * b[j];
        }
        __syncthreads();
    }
    #pragma unroll
    for (int i = 0; i < 4; i++) {
        int gr = row0 + ty * 4 + i;
        if (gr >= M) continue;
        #pragma unroll
        for (int j = 0; j < 4; j++) {
            int gc = col0 + tx * 4 + j;
            if (gc < N) C[(size_t)gr * N + gc] = acc[i][j];
        }
    }
}

// ---------------- el/er for 8-head layers: warp per node ----------------
__global__ void elr8_k(const float* __restrict__ h, const float* __restrict__ al,
                       const float* __restrict__ ar) {
    int w = (blockIdx.x * blockDim.x + threadIdx.x) >> 5;
    int lane = threadIdx.x & 31;
    if (w >= N_NODES) return;
    const float4* hp = (const float4*)(h + (size_t)w * HF + lane * 8);
    float4 a = hp[0], b = hp[1];
    const float4* alp = (const float4*)(al + lane * 8);
    const float4* arp = (const float4*)(ar + lane * 8);
    float4 l0 = alp[0], l1 = alp[1], r0 = arp[0], r1 = arp[1];
    float pel = a.x*l0.x + a.y*l0.y + a.z*l0.z + a.w*l0.w
              + b.x*l1.x + b.y*l1.y + b.z*l1.z + b.w*l1.w;
    float per = a.x*r0.x + a.y*r0.y + a.z*r0.z + a.w*r0.w
              + b.x*r1.x + b.y*r1.y + b.z*r1.z + b.w*r1.w;
    pel += __shfl_xor_sync(0xffffffffu, pel, 1);
    pel += __shfl_xor_sync(0xffffffffu, pel, 2);
    per += __shfl_xor_sync(0xffffffffu, per, 1);
    per += __shfl_xor_sync(0xffffffffu, per, 2);
    if ((lane & 3) == 0) {
        g_el[w * HEADS + (lane >> 2)] = pel;
        g_er[w * HEADS + (lane >> 2)] = per;
    }
}

// ---------------- 8-head aggregation: warp per dst node, two register passes ----------------
__global__ void agg8_k(const float* __restrict__ h, float* __restrict__ out, int do_elu) {
    int w = (blockIdx.x * blockDim.x + threadIdx.x) >> 5;
    int lane = threadIdx.x & 31;
    if (w >= N_NODES) return;
    int head = lane >> 2;
    float erd = g_er[w * HEADS + head];
    int b = g_off[w], e = g_off[w + 1];
    float m = -INFINITY;
    for (int i = b; i < e; i++) {
        int s = g_ssrc[i];
        float v = g_el[s * HEADS + head] + erd;
        v = v > 0.f ? v : NEG_SLOPE * v;
        m = fmaxf(m, v);
    }
    float a0=0,a1=0,a2=0,a3=0,a4=0,a5=0,a6=0,a7=0, ss=0;
    for (int i = b; i < e; i++) {
        int s = g_ssrc[i];
        float v = g_el[s * HEADS + head] + erd;
        v = v > 0.f ? v : NEG_SLOPE * v;
        float ex = __expf(v - m);
        ss += ex;
        const float4* hp = (const float4*)(h + (size_t)s * HF + lane * 8);
        float4 u = hp[0], q = hp[1];
        a0 += ex*u.x; a1 += ex*u.y; a2 += ex*u.z; a3 += ex*u.w;
        a4 += ex*q.x; a5 += ex*q.y; a6 += ex*q.z; a7 += ex*q.w;
    }
    float inv = 1.f / (ss + 1e-16f);
    float r[8] = {a0*inv, a1*inv, a2*inv, a3*inv, a4*inv, a5*inv, a6*inv, a7*inv};
    if (do_elu) {
        #pragma unroll
        for (int k = 0; k < 8; k++) r[k] = r[k] > 0.f ? r[k] : expm1f(r[k]);
    }
    float4* op = (float4*)(out + (size_t)w * HF + lane * 8);
    op[0] = make_float4(r[0], r[1], r[2], r[3]);
    op[1] = make_float4(r[4], r[5], r[6], r[7]);
}

// ---------------- output layer el/er (H=1, F=40): warp per node ----------------
__global__ void elro_k(const float* __restrict__ h, const float* __restrict__ alo,
                       const float* __restrict__ aro) {
    int w = (blockIdx.x * blockDim.x + threadIdx.x) >> 5;
    int lane = threadIdx.x & 31;
    if (w >= N_NODES) return;
    float v1 = h[(size_t)w * N_CLASSES + lane];
    float v2 = (lane < 8) ? h[(size_t)w * N_CLASSES + 32 + lane] : 0.f;
    float pel = v1 * alo[lane] + ((lane < 8) ? v2 * alo[32 + lane] : 0.f);
    float per = v1 * aro[lane] + ((lane < 8) ? v2 * aro[32 + lane] : 0.f);
    #pragma unroll
    for (int d = 16; d >= 1; d >>= 1) {
        pel += __shfl_xor_sync(0xffffffffu, pel, d);
        per += __shfl_xor_sync(0xffffffffu, per, d);
    }
    if (lane == 0) { g_el[w] = pel; g_er[w] = per; }
}

// ---------------- output aggregation (H=1, F=40): warp per dst ----------------
__global__ void agg1_k(const float* __restrict__ h, float* __restrict__ out) {
    int w = (blockIdx.x * blockDim.x + threadIdx.x) >> 5;
    int lane = threadIdx.x & 31;
    if (w >= N_NODES) return;
    float erd = g_er[w];
    int b = g_off[w], e = g_off[w + 1];
    float m = -INFINITY;
    for (int i = b; i < e; i++) {
        int s = g_ssrc[i];
        float v = g_el[s] + erd;
        v = v > 0.f ? v : NEG_SLOPE * v;
        m = fmaxf(m, v);
    }
    float a0 = 0, a1 = 0, ss = 0;
    for (int i = b; i < e; i++) {
        int s = g_ssrc[i];
        float v = g_el[s] + erd;
        v = v > 0.f ? v : NEG_SLOPE * v;
        float ex = __expf(v - m);
        ss += ex;
        a0 += ex * h[(size_t)s * N_CLASSES + lane];
        if (lane < 8) a1 += ex * h[(size_t)s * N_CLASSES + 32 + lane];
    }
    float inv = 1.f / (ss + 1e-16f);
    out[(size_t)w * N_CLASSES + lane] = a0 * inv;
    if (lane < 8) out[(size_t)w * N_CLASSES + 32 + lane] = a1 * inv;
}

// ---------------- log_softmax over 40 classes: warp per node ----------------
__global__ void lsm_k(const float* __restrict__ in, float* __restrict__ out) {
    int w = (blockIdx.x * blockDim.x + threadIdx.x) >> 5;
    int lane = threadIdx.x & 31;
    if (w >= N_NODES) return;
    float v1 = in[(size_t)w * N_CLASSES + lane];
    float v2 = (lane < 8) ? in[(size_t)w * N_CLASSES + 32 + lane] : -INFINITY;
    float m = fmaxf(v1, v2);
    #pragma unroll
    for (int d = 16; d >= 1; d >>= 1) m = fmaxf(m, __shfl_xor_sync(0xffffffffu, m, d));
    float s = expf(v1 - m) + ((lane < 8) ? expf(v2 - m) : 0.f);
    #pragma unroll
    for (int d = 16; d >= 1; d >>= 1) s += __shfl_xor_sync(0xffffffffu, s, d);
    float ls = logf(s) + m;
    out[(size_t)w * N_CLASSES + lane] = v1 - ls;
    if (lane < 8) out[(size_t)w * N_CLASSES + 32 + lane] = v2 - ls;
}

// ---------------- host launcher ----------------
static inline int cdiv(int a, int b) { return (a + b - 1) / b; }

extern "C" void kernel_launch(void* const* d_in, const int* in_sizes, int n_in,
                              void* d_out, int out_size) {
    const float* x   = (const float*)d_in[0];
    const int*   src = (const int*)d_in[1];
    const int*   dst = (const int*)d_in[2];
    const float* W1  = (const float*)d_in[3];
    const float* al1 = (const float*)d_in[4];
    const float* ar1 = (const float*)d_in[5];
    const float* W2  = (const float*)d_in[6];
    const float* ar2_al = (const float*)d_in[7];   // al2
    const float* ar2 = (const float*)d_in[8];
    const float* Wo  = (const float*)d_in[9];
    const float* alo = (const float*)d_in[10];
    const float* aro = (const float*)d_in[11];
    float* out = (float*)d_out;

    void *pP, *pQ, *pO1, *pO2, *pCnt, *pCur;
    cudaGetSymbolAddress(&pP, g_P);
    cudaGetSymbolAddress(&pQ, g_Q);
    cudaGetSymbolAddress(&pO1, g_o1);
    cudaGetSymbolAddress(&pO2, g_o2);
    cudaGetSymbolAddress(&pCnt, g_cnt);
    cudaGetSymbolAddress(&pCur, g_cur);

    // CSR build (by dst)
    cudaMemsetAsync(pCnt, 0, N_NODES * sizeof(int));
    cudaMemsetAsync(pCur, 0, N_NODES * sizeof(int));
    int eb = cdiv(N_EDGES, 256);
    hist_k<<<eb, 256>>>(dst);
    scan_k<<<1, 1024>>>();
    scatter_k<<<eb, 256>>>(src, dst);

    int nwb = cdiv(N_NODES * 32, 256);   // warp-per-node grids

    // layer 1
    gemm_k<<<dim3(cdiv(HF, BN), cdiv(N_NODES, BM)), 256>>>(x, W1, (float*)pP, N_NODES, HF, IN_F);
    elr8_k<<<nwb, 256>>>((const float*)pP, al1, ar1);
    agg8_k<<<nwb, 256>>>((const float*)pP, (float*)pQ, 1);

    // layer 2
    gemm_k<<<dim3(cdiv(HF, BN), cdiv(N_NODES, BM)), 256>>>((const float*)pQ, W2, (float*)pP, N_NODES, HF, HF);
    elr8_k<<<nwb, 256>>>((const float*)pP, ar2_al, ar2);
    agg8_k<<<nwb, 256>>>((const float*)pP, (float*)pQ, 1);

    // output layer
    gemm_k<<<dim3(cdiv(N_CLASSES, BN), cdiv(N_NODES, BM)), 256>>>((const float*)pQ, Wo, (float*)pO1, N_NODES, N_CLASSES, HF);
    elro_k<<<nwb, 256>>>((const float*)pO1, alo, aro);
    agg1_k<<<nwb, 256>>>((const float*)pO1, (float*)pO2);
    lsm_k<<<nwb, 256>>>((const float*)pO2, out);
}

// round 2
// speedup vs baseline: 1.4681x; 1.4681x over previous
#include <cuda_runtime.h>
#include <math.h>

#define N_NODES 50000
#define N_EDGES 800000
#define IN_F    128
#define HID     32
#define HEADS   8
#define HF      256          // HEADS*HID
#define N_CLASSES 40
#define NEG_SLOPE 0.2f

// ---------------- scratch (device globals; no allocation allowed) ----------------
__device__ float g_P[N_NODES * HF];          // projected features
__device__ float g_Q[N_NODES * HF];          // aggregated features
__device__ float g_el[N_NODES * HEADS];
__device__ float g_er[N_NODES * HEADS];
__device__ float g_o1[N_NODES * N_CLASSES];  // output-layer projection
__device__ float g_o2[N_NODES * N_CLASSES];  // output-layer aggregation
__device__ int   g_cnt[N_NODES];
__device__ int   g_cur[N_NODES];
__device__ int   g_off[N_NODES + 1];
__device__ int   g_ssrc[N_EDGES];

// ---------------- CSR build: histogram -> scan -> scatter ----------------
__global__ void hist_k(const int* __restrict__ dst) {
    int i = blockIdx.x * blockDim.x + threadIdx.x;
    if (i < N_EDGES) atomicAdd(&g_cnt[dst[i]], 1);
}

__global__ void scan_k() {   // one block, 1024 threads
    __shared__ int sh[1024];
    int t = threadIdx.x;
    const int n = N_NODES;
    const int chunk = (n + 1023) / 1024;
    int lo = t * chunk;
    int hi = lo + chunk; if (hi > n) hi = n;
    int s = 0;
    for (int i = lo; i < hi; i++) s += g_cnt[i];
    sh[t] = s;
    __syncthreads();
    int own = s;
    for (int d = 1; d < 1024; d <<= 1) {
        int v = (t >= d) ? sh[t - d] : 0;
        __syncthreads();
        sh[t] += v;
        __syncthreads();
    }
    int base = sh[t] - own;
    for (int i = lo; i < hi; i++) { g_off[i] = base; base += g_cnt[i]; }
    if (t == 1023) g_off[n] = sh[1023];
}

__global__ void scatter_k(const int* __restrict__ src, const int* __restrict__ dst) {
    int i = blockIdx.x * blockDim.x + threadIdx.x;
    if (i < N_EDGES) {
        int d = dst[i];
        int pos = atomicAdd(&g_cur[d], 1);
        g_ssrc[g_off[d] + pos] = src[i];
    }
}

// ---------------- TF32 tensor-core GEMM: C[M,N] = A[M,K] @ B[K,N] ----------------
__device__ __forceinline__ unsigned f2tf(float x) {
    unsigned r; asm("cvt.rna.tf32.f32 %0, %1;" : "=r"(r) : "f"(x)); return r;
}

#define TBM 128
#define TBN 64
#define TBK 16
#define ASTR (TBM + 8)   // 136: staging stores (8k+r)%32 distinct; frag loads (8t+g)%32 distinct
#define BSTR (TBN + 8)   // 72: same property

__global__ __launch_bounds__(256) void gemm_tc(const float* __restrict__ A,
                                               const float* __restrict__ B,
                                               float* __restrict__ C,
                                               int M, int N, int K) {
    __shared__ unsigned As[TBK * ASTR];
    __shared__ unsigned Bs[TBK * BSTR];
    int tid = threadIdx.x;
    int lane = tid & 31, warp = tid >> 5;
    int wm = warp & 3, wn = warp >> 2;       // 4 (m) x 2 (n) warp grid
    int g = lane >> 2, t = lane & 3;
    int row0 = blockIdx.y * TBM, col0 = blockIdx.x * TBN;

    float c[2][4][4];
    #pragma unroll
    for (int i = 0; i < 2; i++)
        #pragma unroll
        for (int j = 0; j < 4; j++)
            #pragma unroll
            for (int k = 0; k < 4; k++) c[i][j][k] = 0.f;

    for (int k0 = 0; k0 < K; k0 += TBK) {
        // stage A tile [TBM x TBK], k-major in smem: As[k][m]
        #pragma unroll
        for (int i = 0; i < 2; i++) {
            int idx = tid + i * 256;
            int r  = idx & 127;
            int kq = (idx >> 7) << 2;
            int gr = row0 + r;
            float4 v = make_float4(0.f, 0.f, 0.f, 0.f);
            if (gr < M) v = *(const float4*)(A + (size_t)gr * K + k0 + kq);
            As[(kq + 0) * ASTR + r] = f2tf(v.x);
            As[(kq + 1) * ASTR + r] = f2tf(v.y);
            As[(kq + 2) * ASTR + r] = f2tf(v.z);
            As[(kq + 3) * ASTR + r] = f2tf(v.w);
        }
        // stage B tile [TBK x TBN]: Bs[k][n]
        {
            int r  = tid >> 4;
            int nq = (tid & 15) << 2;
            int gc = col0 + nq;
            float4 v = make_float4(0.f, 0.f, 0.f, 0.f);
            const float* bp = B + (size_t)(k0 + r) * N;
            if (gc + 3 < N) {
                v = *(const float4*)(bp + gc);
            } else {
                if (gc     < N) v.x = bp[gc];
                if (gc + 1 < N) v.y = bp[gc + 1];
                if (gc + 2 < N) v.z = bp[gc + 2];
            }
            Bs[r * BSTR + nq + 0] = f2tf(v.x);
            Bs[r * BSTR + nq + 1] = f2tf(v.y);
            Bs[r * BSTR + nq + 2] = f2tf(v.z);
            Bs[r * BSTR + nq + 3] = f2tf(v.w);
        }
        __syncthreads();

        #pragma unroll
        for (int ks = 0; ks < 2; ks++) {
            int kb = ks * 8;
            unsigned a[2][4], b[4][2];
            #pragma unroll
            for (int mt = 0; mt < 2; mt++) {
                int m0 = wm * 32 + mt * 16;
                a[mt][0] = As[(kb + t)     * ASTR + m0 + g];
                a[mt][1] = As[(kb + t)     * ASTR + m0 + g + 8];
                a[mt][2] = As[(kb + t + 4) * ASTR + m0 + g];
                a[mt][3] = As[(kb + t + 4) * ASTR + m0 + g + 8];
            }
            #pragma unroll
            for (int nt = 0; nt < 4; nt++) {
                int n0 = wn * 32 + nt * 8;
                b[nt][0] = Bs[(kb + t)     * BSTR + n0 + g];
                b[nt][1] = Bs[(kb + t + 4) * BSTR + n0 + g];
            }
            #pragma unroll
            for (int mt = 0; mt < 2; mt++)
                #pragma unroll
                for (int nt = 0; nt < 4; nt++)
                    asm volatile(
                        "mma.sync.aligned.m16n8k8.row.col.f32.tf32.tf32.f32 "
                        "{%0,%1,%2,%3},{%4,%5,%6,%7},{%8,%9},{%0,%1,%2,%3};"
                        : "+f"(c[mt][nt][0]), "+f"(c[mt][nt][1]),
                          "+f"(c[mt][nt][2]), "+f"(c[mt][nt][3])
                        : "r"(a[mt][0]), "r"(a[mt][1]), "r"(a[mt][2]), "r"(a[mt][3]),
                          "r"(b[nt][0]), "r"(b[nt][1]));
        }
        __syncthreads();
    }

    // epilogue: c0:(g,2t) c1:(g,2t+1) c2:(g+8,2t) c3:(g+8,2t+1)
    #pragma unroll
    for (int mt = 0; mt < 2; mt++) {
        int rr = row0 + wm * 32 + mt * 16 + g;
        #pragma unroll
        for (int nt = 0; nt < 4; nt++) {
            int cc = col0 + wn * 32 + nt * 8 + 2 * t;
            if (rr < M) {
                if (cc     < N) C[(size_t)rr * N + cc]     = c[mt][nt][0];
                if (cc + 1 < N) C[(size_t)rr * N + cc + 1] = c[mt][nt][1];
            }
            if (rr + 8 < M) {
                if (cc     < N) C[(size_t)(rr + 8) * N + cc]     = c[mt][nt][2];
                if (cc + 1 < N) C[(size_t)(rr + 8) * N + cc + 1] = c[mt][nt][3];
            }
        }
    }
}

// ---------------- el/er for 8-head layers: warp per node ----------------
__global__ void elr8_k(const float* __restrict__ h, const float* __restrict__ al,
                       const float* __restrict__ ar) {
    int w = (blockIdx.x * blockDim.x + threadIdx.x) >> 5;
    int lane = threadIdx.x & 31;
    if (w >= N_NODES) return;
    const float4* hp = (const float4*)(h + (size_t)w * HF + lane * 8);
    float4 a = hp[0], b = hp[1];
    const float4* alp = (const float4*)(al + lane * 8);
    const float4* arp = (const float4*)(ar + lane * 8);
    float4 l0 = alp[0], l1 = alp[1], r0 = arp[0], r1 = arp[1];
    float pel = a.x*l0.x + a.y*l0.y + a.z*l0.z + a.w*l0.w
              + b.x*l1.x + b.y*l1.y + b.z*l1.z + b.w*l1.w;
    float per = a.x*r0.x + a.y*r0.y + a.z*r0.z + a.w*r0.w
              + b.x*r1.x + b.y*r1.y + b.z*r1.z + b.w*r1.w;
    pel += __shfl_xor_sync(0xffffffffu, pel, 1);
    pel += __shfl_xor_sync(0xffffffffu, pel, 2);
    per += __shfl_xor_sync(0xffffffffu, per, 1);
    per += __shfl_xor_sync(0xffffffffu, per, 2);
    if ((lane & 3) == 0) {
        g_el[w * HEADS + (lane >> 2)] = pel;
        g_er[w * HEADS + (lane >> 2)] = per;
    }
}

// ---------------- 8-head aggregation: warp per dst node, two register passes ----------------
__global__ void agg8_k(const float* __restrict__ h, float* __restrict__ out, int do_elu) {
    int w = (blockIdx.x * blockDim.x + threadIdx.x) >> 5;
    int lane = threadIdx.x & 31;
    if (w >= N_NODES) return;
    int head = lane >> 2;
    float erd = g_er[w * HEADS + head];
    int b = g_off[w], e = g_off[w + 1];
    float m = -INFINITY;
    for (int i = b; i < e; i++) {
        int s = g_ssrc[i];
        float v = g_el[s * HEADS + head] + erd;
        v = v > 0.f ? v : NEG_SLOPE * v;
        m = fmaxf(m, v);
    }
    float a0=0,a1=0,a2=0,a3=0,a4=0,a5=0,a6=0,a7=0, ss=0;
    for (int i = b; i < e; i++) {
        int s = g_ssrc[i];
        float v = g_el[s * HEADS + head] + erd;
        v = v > 0.f ? v : NEG_SLOPE * v;
        float ex = __expf(v - m);
        ss += ex;
        const float4* hp = (const float4*)(h + (size_t)s * HF + lane * 8);
        float4 u = hp[0], q = hp[1];
        a0 += ex*u.x; a1 += ex*u.y; a2 += ex*u.z; a3 += ex*u.w;
        a4 += ex*q.x; a5 += ex*q.y; a6 += ex*q.z; a7 += ex*q.w;
    }
    float inv = 1.f / (ss + 1e-16f);
    float r[8] = {a0*inv, a1*inv, a2*inv, a3*inv, a4*inv, a5*inv, a6*inv, a7*inv};
    if (do_elu) {
        #pragma unroll
        for (int k = 0; k < 8; k++) r[k] = r[k] > 0.f ? r[k] : expm1f(r[k]);
    }
    float4* op = (float4*)(out + (size_t)w * HF + lane * 8);
    op[0] = make_float4(r[0], r[1], r[2], r[3]);
    op[1] = make_float4(r[4], r[5], r[6], r[7]);
}

// ---------------- output layer el/er (H=1, F=40): warp per node ----------------
__global__ void elro_k(const float* __restrict__ h, const float* __restrict__ alo,
                       const float* __restrict__ aro) {
    int w = (blockIdx.x * blockDim.x + threadIdx.x) >> 5;
    int lane = threadIdx.x & 31;
    if (w >= N_NODES) return;
    float v1 = h[(size_t)w * N_CLASSES + lane];
    float v2 = (lane < 8) ? h[(size_t)w * N_CLASSES + 32 + lane] : 0.f;
    float pel = v1 * alo[lane] + ((lane < 8) ? v2 * alo[32 + lane] : 0.f);
    float per = v1 * aro[lane] + ((lane < 8) ? v2 * aro[32 + lane] : 0.f);
    #pragma unroll
    for (int d = 16; d >= 1; d >>= 1) {
        pel += __shfl_xor_sync(0xffffffffu, pel, d);
        per += __shfl_xor_sync(0xffffffffu, per, d);
    }
    if (lane == 0) { g_el[w] = pel; g_er[w] = per; }
}

// ---------------- output aggregation (H=1, F=40): warp per dst ----------------
__global__ void agg1_k(const float* __restrict__ h, float* __restrict__ out) {
    int w = (blockIdx.x * blockDim.x + threadIdx.x) >> 5;
    int lane = threadIdx.x & 31;
    if (w >= N_NODES) return;
    float erd = g_er[w];
    int b = g_off[w], e = g_off[w + 1];
    float m = -INFINITY;
    for (int i = b; i < e; i++) {
        int s = g_ssrc[i];
        float v = g_el[s] + erd;
        v = v > 0.f ? v : NEG_SLOPE * v;
        m = fmaxf(m, v);
    }
    float a0 = 0, a1 = 0, ss = 0;
    for (int i = b; i < e; i++) {
        int s = g_ssrc[i];
        float v = g_el[s] + erd;
        v = v > 0.f ? v : NEG_SLOPE * v;
        float ex = __expf(v - m);
        ss += ex;
        a0 += ex * h[(size_t)s * N_CLASSES + lane];
        if (lane < 8) a1 += ex * h[(size_t)s * N_CLASSES + 32 + lane];
    }
    float inv = 1.f / (ss + 1e-16f);
    out[(size_t)w * N_CLASSES + lane] = a0 * inv;
    if (lane < 8) out[(size_t)w * N_CLASSES + 32 + lane] = a1 * inv;
}

// ---------------- log_softmax over 40 classes: warp per node ----------------
__global__ void lsm_k(const float* __restrict__ in, float* __restrict__ out) {
    int w = (blockIdx.x * blockDim.x + threadIdx.x) >> 5;
    int lane = threadIdx.x & 31;
    if (w >= N_NODES) return;
    float v1 = in[(size_t)w * N_CLASSES + lane];
    float v2 = (lane < 8) ? in[(size_t)w * N_CLASSES + 32 + lane] : -INFINITY;
    float m = fmaxf(v1, v2);
    #pragma unroll
    for (int d = 16; d >= 1; d >>= 1) m = fmaxf(m, __shfl_xor_sync(0xffffffffu, m, d));
    float s = expf(v1 - m) + ((lane < 8) ? expf(v2 - m) : 0.f);
    #pragma unroll
    for (int d = 16; d >= 1; d >>= 1) s += __shfl_xor_sync(0xffffffffu, s, d);
    float ls = logf(s) + m;
    out[(size_t)w * N_CLASSES + lane] = v1 - ls;
    if (lane < 8) out[(size_t)w * N_CLASSES + 32 + lane] = v2 - ls;
}

// ---------------- host launcher ----------------
static inline int cdiv(int a, int b) { return (a + b - 1) / b; }

extern "C" void kernel_launch(void* const* d_in, const int* in_sizes, int n_in,
                              void* d_out, int out_size) {
    const float* x   = (const float*)d_in[0];
    const int*   src = (const int*)d_in[1];
    const int*   dst = (const int*)d_in[2];
    const float* W1  = (const float*)d_in[3];
    const float* al1 = (const float*)d_in[4];
    const float* ar1 = (const float*)d_in[5];
    const float* W2  = (const float*)d_in[6];
    const float* al2 = (const float*)d_in[7];
    const float* ar2 = (const float*)d_in[8];
    const float* Wo  = (const float*)d_in[9];
    const float* alo = (const float*)d_in[10];
    const float* aro = (const float*)d_in[11];
    float* out = (float*)d_out;

    void *pP, *pQ, *pO1, *pO2, *pCnt, *pCur;
    cudaGetSymbolAddress(&pP, g_P);
    cudaGetSymbolAddress(&pQ, g_Q);
    cudaGetSymbolAddress(&pO1, g_o1);
    cudaGetSymbolAddress(&pO2, g_o2);
    cudaGetSymbolAddress(&pCnt, g_cnt);
    cudaGetSymbolAddress(&pCur, g_cur);

    // CSR build (by dst)
    cudaMemsetAsync(pCnt, 0, N_NODES * sizeof(int));
    cudaMemsetAsync(pCur, 0, N_NODES * sizeof(int));
    int eb = cdiv(N_EDGES, 256);
    hist_k<<<eb, 256>>>(dst);
    scan_k<<<1, 1024>>>();
    scatter_k<<<eb, 256>>>(src, dst);

    int nwb = cdiv(N_NODES * 32, 256);   // warp-per-node grids
    dim3 g1(cdiv(HF, TBN), cdiv(N_NODES, TBM));
    dim3 g3(cdiv(N_CLASSES, TBN), cdiv(N_NODES, TBM));

    // layer 1
    gemm_tc<<<g1, 256>>>(x, W1, (float*)pP, N_NODES, HF, IN_F);
    elr8_k<<<nwb, 256>>>((const float*)pP, al1, ar1);
    agg8_k<<<nwb, 256>>>((const float*)pP, (float*)pQ, 1);

    // layer 2
    gemm_tc<<<g1, 256>>>((const float*)pQ, W2, (float*)pP, N_NODES, HF, HF);
    elr8_k<<<nwb, 256>>>((const float*)pP, al2, ar2);
    agg8_k<<<nwb, 256>>>((const float*)pP, (float*)pQ, 1);

    // output layer
    gemm_tc<<<g3, 256>>>((const float*)pQ, Wo, (float*)pO1, N_NODES, N_CLASSES, HF);
    elro_k<<<nwb, 256>>>((const float*)pO1, alo, aro);
    agg1_k<<<nwb, 256>>>((const float*)pO1, (float*)pO2);
    lsm_k<<<nwb, 256>>>((const float*)pO2, out);
}